// round 16
// baseline (speedup 1.0000x reference)
#include <cuda_runtime.h>
#include <math.h>
#include <stdint.h>

#define B 8
#define D 256
#define NTOT 10790            // 2*(4096+1024+256) + 3 + 3 + 32
#define TOK_K 32
#define POFF_FG 10752
#define POFF_BG 10755
#define TOK_OFF 10758
#define UPLANE 10752          // per-(b,comp) u plane: q(5376)+s(5376) pixel slots
#define NCHUNK 8              // channel chunks in rank2 phase (32 ch each)

__device__ __forceinline__ int lv_hw(int lv)   { return 4096 >> (2 * lv); }
__device__ __forceinline__ int lv_w(int lv)    { return 64 >> lv; }
__device__ __forceinline__ int lv_fac(int lv)  { return 8 << lv; }
__device__ __forceinline__ int lv_moff(int lv) { return lv == 0 ? 0 : (lv == 1 ? 32768 : 40960); }

__device__ __constant__ int c_offQ[3] = {0, 4096, 5120};
__device__ __constant__ int c_offS[3] = {5376, 9472, 10496};

// Scratch (static device globals: allocation-free)
__device__ __align__(16) float g_mask[43008];
__device__ float g_cnt[3][B];
__device__ float g_sumfg[3][2][B][D];      // [lv][pixel-half][b][ch]
__device__ float g_sumall[3][2][B][D];
__device__ float g_D[3][B][2][D];
__device__ float g_Rn[3][2][D];
__device__ float g_E[3];
__device__ __align__(16) float g_upart[NCHUNK][B][2][UPLANE];
__device__ __align__(16) float g_u[B][2][UPLANE];

__device__ __forceinline__ float warpSum(float v) {
#pragma unroll
    for (int o = 16; o; o >>= 1) v += __shfl_xor_sync(0xffffffffu, v, o);
    return v;
}

// ---------------------------------------------------------------------------
// 1) fused: nearest-downsample mask + per-(b,lv) fg count
__global__ void k_mask(const int* __restrict__ sm) {
    int b = blockIdx.x, lv = blockIdx.y, tid = threadIdx.x;
    int hw = lv_hw(lv), w = lv_w(lv), f = lv_fac(lv), moff = lv_moff(lv);
    float c = 0.f;
    for (int t = tid; t < hw; t += 256) {
        int y = t / w, x = t % w;
        float v = (float)sm[((size_t)b * 512 + (size_t)y * f) * 512 + (size_t)x * f];
        g_mask[moff + b * hw + t] = v;
        c += v;
    }
    c = warpSum(c);
    __shared__ float red[8];
    if ((tid & 31) == 0) red[tid >> 5] = c;
    __syncthreads();
    if (tid == 0) {
        float s = 0.f;
#pragma unroll
        for (int i = 0; i < 8; i++) s += red[i];
        g_cnt[lv][b] = s;
    }
}

// ---------------------------------------------------------------------------
// 2) prototype sums: one block per (channel, b, lv*2+half), __ldcs streaming
__global__ void k_proto(const float* __restrict__ s0, const float* __restrict__ s1,
                        const float* __restrict__ s2) {
    int ch = blockIdx.x, b = blockIdx.y, z = blockIdx.z, tid = threadIdx.x;
    int lv = z >> 1, half = z & 1;
    int hw = lv_hw(lv), h4 = hw >> 3;          // float4 elems per half
    const float* s = (lv == 0) ? s0 : (lv == 1 ? s1 : s2);
    const float4* row = (const float4*)(s + ((size_t)(b * D + ch)) * hw) + half * h4;
    const float4* m = (const float4*)(g_mask + lv_moff(lv) + b * hw) + half * h4;
    float sf = 0.f, sa = 0.f;
    for (int t = tid; t < h4; t += 128) {
        float4 x = __ldcs(row + t);
        float4 mm = m[t];
        sf += x.x * mm.x + x.y * mm.y + x.z * mm.z + x.w * mm.w;
        sa += x.x + x.y + x.z + x.w;
    }
    sf = warpSum(sf); sa = warpSum(sa);
    __shared__ float r1[4], r2[4];
    if ((tid & 31) == 0) { r1[tid >> 5] = sf; r2[tid >> 5] = sa; }
    __syncthreads();
    if (tid == 0) {
        g_sumfg[lv][half][b][ch]  = r1[0] + r1[1] + r1[2] + r1[3];
        g_sumall[lv][half][b][ch] = r2[0] + r2[1] + r2[2] + r2[3];
    }
}

// ---------------------------------------------------------------------------
// 3) prep: one WARP per (b,lv). 8 channels/thread, pure shfl reductions.
__global__ void k_prep(const float* __restrict__ r0, const float* __restrict__ r1,
                       const float* __restrict__ r2, float* __restrict__ out) {
    int b = blockIdx.x, lv = blockIdx.y, t = threadIdx.x;
    const float* R = (lv == 0) ? r0 : (lv == 1 ? r1 : r2);
    float cnt = g_cnt[lv][b];
    float hwf = (float)lv_hw(lv);

    float pf[8], pb[8], rn0[8], rn1[8], c0[8], c1[8], d0[8], d1[8];
    float nf = 0.f, nb = 0.f, nr0 = 0.f, nr1 = 0.f;
#pragma unroll
    for (int j = 0; j < 8; j++) {
        int c = t + 32 * j;
        float sfg = g_sumfg[lv][0][b][c] + g_sumfg[lv][1][b][c];
        float sal = g_sumall[lv][0][b][c] + g_sumall[lv][1][b][c];
        pf[j] = sfg / (cnt + 1e-6f);
        pb[j] = (sal - sfg) / (hwf - cnt + 1e-6f);
        nf += pf[j] * pf[j]; nb += pb[j] * pb[j];
        float v0 = R[c], v1 = R[D + c];
        rn0[j] = v0; rn1[j] = v1;
        nr0 += v0 * v0; nr1 += v1 * v1;
    }
    nf = warpSum(nf); nb = warpSum(nb); nr0 = warpSum(nr0); nr1 = warpSum(nr1);
    float sf_ = sqrtf(nf) + 1e-6f, sb_ = sqrtf(nb) + 1e-6f;
    float sr0 = sqrtf(nr0) + 1e-6f, sr1 = sqrtf(nr1) + 1e-6f;

    float m00 = 0.f, m01 = 0.f, m11 = 0.f;
#pragma unroll
    for (int j = 0; j < 8; j++) {
        c1[j] = pf[j] / sf_;
        c0[j] = pb[j] / sb_;
        rn0[j] = rn0[j] / sr0;
        rn1[j] = rn1[j] / sr1;
        m00 += c0[j] * c0[j]; m01 += c0[j] * c1[j]; m11 += c1[j] * c1[j];
    }
    m00 = warpSum(m00); m01 = warpSum(m01); m11 = warpSum(m11);
    float det = m00 * m11 - m01 * m01;
    float i00 = m11 / det, i01 = -m01 / det, i11 = m00 / det;

    float uf0 = 0.f, uf1 = 0.f, ub0 = 0.f, ub1 = 0.f;
#pragma unroll
    for (int j = 0; j < 8; j++) {
        int c = t + 32 * j;
        d0[j] = i00 * c0[j] + i01 * c1[j];
        d1[j] = i01 * c0[j] + i11 * c1[j];
        g_D[lv][b][0][c] = d0[j];
        g_D[lv][b][1][c] = d1[j];
        if (b == 0) { g_Rn[lv][0][c] = rn0[j]; g_Rn[lv][1][c] = rn1[j]; }
        uf0 += d0[j] * pf[j]; uf1 += d1[j] * pf[j];
        ub0 += d0[j] * pb[j]; ub1 += d1[j] * pb[j];
    }
    uf0 = warpSum(uf0); uf1 = warpSum(uf1);
    ub0 = warpSum(ub0); ub1 = warpSum(ub1);

    if (b == 0 && lv == 0) {
        float e00 = 0.f, e01 = 0.f, e11 = 0.f;
#pragma unroll
        for (int j = 0; j < 8; j++) {
            e00 += rn0[j] * rn0[j]; e01 += rn0[j] * rn1[j]; e11 += rn1[j] * rn1[j];
        }
        e00 = warpSum(e00); e01 = warpSum(e01); e11 = warpSum(e11);
        if (t == 0) { g_E[0] = e00; g_E[1] = e01; g_E[2] = e11; }
    }

#pragma unroll
    for (int j = 0; j < 8; j++) {
        int c = t + 32 * j;
        size_t rowbase = (size_t)(b * D + c) * NTOT;
        out[rowbase + POFF_FG + lv] = rn0[j] * uf0 + rn1[j] * uf1;
        out[rowbase + POFF_BG + lv] = rn0[j] * ub0 + rn1[j] * ub1;
    }
}

// ---------------------------------------------------------------------------
// 4a) Phase A: partial u over 32-channel chunk.
//     Exact flattened grid: 6 slots per (b,which): lv0 4 tiles, lv1 1, lv2 1.
//     grid (6, NCHUNK, 16). All loads __ldcs streaming.
__global__ void k_rank2(const float* __restrict__ q0, const float* __restrict__ q1,
                        const float* __restrict__ q2, const float* __restrict__ s0,
                        const float* __restrict__ s1, const float* __restrict__ s2) {
    int z = blockIdx.z;
    int b = z >> 1, which = z & 1;
    int slot = blockIdx.x;                 // 0..5
    int lv, tile;
    if (slot < 4)       { lv = 0; tile = slot * 256; }
    else if (slot == 4) { lv = 1; tile = 0; }
    else                { lv = 2; tile = 0; }
    int hw = lv_hw(lv), hw4 = hw >> 2;
    int chunk = blockIdx.y, cbase = chunk * 32;
    int tid = threadIdx.x;

    __shared__ float sD0[32], sD1[32];
    if (tid < 32) {
        sD0[tid] = g_D[lv][b][0][cbase + tid];
        sD1[tid] = g_D[lv][b][1][cbase + tid];
    }
    __syncthreads();

    int p = tile + tid;
    if (p >= hw4) return;

    const float* f = (which == 0) ? (lv == 0 ? q0 : (lv == 1 ? q1 : q2))
                                  : (lv == 0 ? s0 : (lv == 1 ? s1 : s2));
    const float4* base = (const float4*)(f + (size_t)b * D * hw + (size_t)cbase * hw) + p;

    float u0x = 0.f, u0y = 0.f, u0z = 0.f, u0w = 0.f;
    float u1x = 0.f, u1y = 0.f, u1z = 0.f, u1w = 0.f;
#pragma unroll 16
    for (int i = 0; i < 32; i++) {
        float4 x = __ldcs(base + (size_t)i * hw4);
        float dd0 = sD0[i], dd1 = sD1[i];
        u0x += dd0 * x.x; u0y += dd0 * x.y; u0z += dd0 * x.z; u0w += dd0 * x.w;
        u1x += dd1 * x.x; u1y += dd1 * x.y; u1z += dd1 * x.z; u1w += dd1 * x.w;
    }

    int uoff = (which == 0) ? c_offQ[lv] : c_offS[lv];
    ((float4*)(g_upart[chunk][b][0] + uoff))[p] = make_float4(u0x, u0y, u0z, u0w);
    ((float4*)(g_upart[chunk][b][1] + uoff))[p] = make_float4(u1x, u1y, u1z, u1w);
}

// ---------------------------------------------------------------------------
// 4b) usum + topk in one launch.
//     Blocks 0..335: chunk fold (g_u = sum of 8 partials), float2 granularity.
//     Blocks 336..343: top-32 for batch b = x-336, reading g_upart directly
//     (same summation order as the fold -> bitwise-identical u values), so
//     there is NO dependency on the fold blocks.
__global__ void k_usum_topk(float* __restrict__ out) {
    int bx = blockIdx.x, tid = threadIdx.x;

    if (bx < 336) {
        int idx = bx * 256 + tid;                      // float2 index
        const int P2 = UPLANE / 2;                      // 5376
        int plane = idx / P2, i = idx % P2;
        int b = plane >> 1, comp = plane & 1;
        float2 a = make_float2(0.f, 0.f);
#pragma unroll
        for (int c = 0; c < NCHUNK; c++) {
            float2 v = ((const float2*)g_upart[c][b][comp])[i];
            a.x += v.x; a.y += v.y;
        }
        ((float2*)g_u[b][comp])[i] = a;
        return;
    }

    // ---- top-k path ----
    int b = bx - 336;
    int lane = tid & 31, wrp = tid >> 5;
    __shared__ unsigned long long swk[8];
    __shared__ unsigned long long s_best;
    __shared__ int s_idx[TOK_K];

    float cnt = g_cnt[0][b];
    float e00 = g_E[0], e01 = g_E[1], e11 = g_E[2];
    const float* m = g_mask + b * 4096;
    const int S0 = 5376;   // s lv0 offset in u plane

    unsigned long long key[16];
#pragma unroll
    for (int j = 0; j < 16; j++) {
        int t = tid + 256 * j;
        float u0 = 0.f, u1 = 0.f;
#pragma unroll
        for (int c = 0; c < NCHUNK; c++) {
            u0 += g_upart[c][b][0][S0 + t];
            u1 += g_upart[c][b][1][S0 + t];
        }
        float s2 = e00 * u0 * u0 + 2.f * e01 * u0 * u1 + e11 * u1 * u1;
        bool valid = (cnt > 0.f) ? (m[t] >= 0.5f) : true;   // fallback_to_full
        unsigned int fb = __float_as_uint(s2);
        fb = (fb & 0x80000000u) ? ~fb : (fb | 0x80000000u); // sortable float bits
        unsigned int il = ~(unsigned int)t;                 // tie: lower idx wins
        key[j] = valid ? (((unsigned long long)fb << 32) | il)
                       : (unsigned long long)il;            // "-inf": high word 0
    }

    for (int sel = 0; sel < TOK_K; sel++) {
        unsigned long long mk = 0;
#pragma unroll
        for (int j = 0; j < 16; j++) mk = (key[j] > mk) ? key[j] : mk;
#pragma unroll
        for (int o = 16; o; o >>= 1) {
            unsigned long long other = __shfl_xor_sync(0xffffffffu, mk, o);
            if (other > mk) mk = other;
        }
        if (lane == 0) swk[wrp] = mk;
        __syncthreads();
        if (tid == 0) {
            unsigned long long best = swk[0];
#pragma unroll
            for (int w = 1; w < 8; w++) if (swk[w] > best) best = swk[w];
            s_best = best;
            s_idx[sel] = (int)(~(unsigned int)(best & 0xffffffffu));
        }
        __syncthreads();
        unsigned long long best = s_best;
#pragma unroll
        for (int j = 0; j < 16; j++) if (key[j] == best) key[j] = 0ull;
        __syncthreads();
    }

    // gather token columns: tid = channel (sum partials, same order as fold)
    float rn0 = g_Rn[0][0][tid], rn1 = g_Rn[0][1][tid];
    size_t rowbase = (size_t)(b * D + tid) * NTOT + TOK_OFF;
#pragma unroll
    for (int j = 0; j < TOK_K; j++) {
        int id = s_idx[j];
        float u0 = 0.f, u1 = 0.f;
#pragma unroll
        for (int c = 0; c < NCHUNK; c++) {
            u0 += g_upart[c][b][0][S0 + id];
            u1 += g_upart[c][b][1][S0 + id];
        }
        out[rowbase + j] = rn0 * u0 + rn1 * u1;
    }
}

// ---------------------------------------------------------------------------
// 5) Phase B: out[i,p] = R0[i]*u0[p] + R1[i]*u1[p]. Streaming stores.
//    Exact flattened grid: 11 active tiles per (b,which): lv0 8, lv1 2, lv2 1.
__global__ void k_expand(float* __restrict__ out) {
    int z = blockIdx.z;
    int b = z >> 1, which = z & 1;
    int tslot = blockIdx.x;                 // 0..10
    int lv, tile;
    if (tslot < 8)      { lv = 0; tile = tslot * 512; }
    else if (tslot < 10){ lv = 1; tile = (tslot - 8) * 512; }
    else                { lv = 2; tile = 0; }
    int hw = lv_hw(lv);
    int tid = threadIdx.x;
    int npix2 = min(512, hw - tile) >> 1;          // float2 slots (<=256)

    __shared__ float sR0[16], sR1[16];
    int ch0 = blockIdx.y * 16;
    if (tid < 16)          sR0[tid]      = g_Rn[lv][0][ch0 + tid];
    else if (tid < 32)     sR1[tid - 16] = g_Rn[lv][1][ch0 + tid - 16];
    __syncthreads();
    if (tid >= npix2) return;

    int uoff = (which == 0) ? c_offQ[lv] : c_offS[lv];
    float2 u0 = ((const float2*)(g_u[b][0] + uoff + tile))[tid];
    float2 u1 = ((const float2*)(g_u[b][1] + uoff + tile))[tid];

    size_t base = (size_t)(b * D + ch0) * NTOT + uoff + tile + 2 * tid;
#pragma unroll
    for (int i = 0; i < 16; i++) {
        float r0 = sR0[i], r1 = sR1[i];
        __stcs((float2*)(out + base + (size_t)i * NTOT),
               make_float2(r0 * u0.x + r1 * u1.x, r0 * u0.y + r1 * u1.y));
    }
}

// ---------------------------------------------------------------------------
extern "C" void kernel_launch(void* const* d_in, const int* in_sizes, int n_in,
                              void* d_out, int out_size) {
    const float *q[3], *s[3], *r[3];
    if (in_sizes[1] == 8388608) {        // dict order q1,s1,r1,q2,s2,r2,q3,s3,r3
        q[0] = (const float*)d_in[0]; s[0] = (const float*)d_in[1]; r[0] = (const float*)d_in[2];
        q[1] = (const float*)d_in[3]; s[1] = (const float*)d_in[4]; r[1] = (const float*)d_in[5];
        q[2] = (const float*)d_in[6]; s[2] = (const float*)d_in[7]; r[2] = (const float*)d_in[8];
    } else {                             // signature order q1,q2,q3,s1,s2,s3,r1,r2,r3
        q[0] = (const float*)d_in[0]; q[1] = (const float*)d_in[1]; q[2] = (const float*)d_in[2];
        s[0] = (const float*)d_in[3]; s[1] = (const float*)d_in[4]; s[2] = (const float*)d_in[5];
        r[0] = (const float*)d_in[6]; r[1] = (const float*)d_in[7]; r[2] = (const float*)d_in[8];
    }
    const int* sm = (const int*)d_in[9];
    float* out = (float*)d_out;

    k_mask<<<dim3(B, 3), 256>>>(sm);
    k_proto<<<dim3(D, B, 6), 128>>>(s[0], s[1], s[2]);
    k_prep<<<dim3(B, 3), 32>>>(r[0], r[1], r[2], out);
    k_rank2<<<dim3(6, NCHUNK, 16), 256>>>(q[0], q[1], q[2], s[0], s[1], s[2]);
    k_usum_topk<<<344, 256>>>(out);
    k_expand<<<dim3(11, 16, 16), 256>>>(out);
}

// round 17
// speedup vs baseline: 1.2218x; 1.2218x over previous
#include <cuda_runtime.h>
#include <math.h>
#include <stdint.h>

#define B 8
#define D 256
#define NTOT 10790            // 2*(4096+1024+256) + 3 + 3 + 32
#define TOK_K 32
#define POFF_FG 10752
#define POFF_BG 10755
#define TOK_OFF 10758
#define UPLANE 10752          // per-(b,comp) u plane: q(5376)+s(5376) pixel slots
#define NCHUNK 8              // channel chunks in rank2 phase (32 ch each)

__device__ __forceinline__ int lv_hw(int lv)   { return 4096 >> (2 * lv); }
__device__ __forceinline__ int lv_w(int lv)    { return 64 >> lv; }
__device__ __forceinline__ int lv_fac(int lv)  { return 8 << lv; }
__device__ __forceinline__ int lv_moff(int lv) { return lv == 0 ? 0 : (lv == 1 ? 32768 : 40960); }

__device__ __constant__ int c_offQ[3] = {0, 4096, 5120};
__device__ __constant__ int c_offS[3] = {5376, 9472, 10496};

// Scratch (static device globals: allocation-free)
__device__ __align__(16) float g_mask[43008];
__device__ float g_cnt[3][B];
__device__ float g_sumfg[3][2][B][D];      // [lv][pixel-half][b][ch]
__device__ float g_sumall[3][2][B][D];
__device__ float g_D[3][B][2][D];
__device__ float g_Rn[3][2][D];
__device__ float g_E[3];
__device__ __align__(16) float g_upart[NCHUNK][B][2][UPLANE];
__device__ __align__(16) float g_u[B][2][UPLANE];

__device__ __forceinline__ float warpSum(float v) {
#pragma unroll
    for (int o = 16; o; o >>= 1) v += __shfl_xor_sync(0xffffffffu, v, o);
    return v;
}

// ---------------------------------------------------------------------------
// 1) fused: nearest-downsample mask + per-(b,lv) fg count
__global__ void k_mask(const int* __restrict__ sm) {
    int b = blockIdx.x, lv = blockIdx.y, tid = threadIdx.x;
    int hw = lv_hw(lv), w = lv_w(lv), f = lv_fac(lv), moff = lv_moff(lv);
    float c = 0.f;
    for (int t = tid; t < hw; t += 256) {
        int y = t / w, x = t % w;
        float v = (float)sm[((size_t)b * 512 + (size_t)y * f) * 512 + (size_t)x * f];
        g_mask[moff + b * hw + t] = v;
        c += v;
    }
    c = warpSum(c);
    __shared__ float red[8];
    if ((tid & 31) == 0) red[tid >> 5] = c;
    __syncthreads();
    if (tid == 0) {
        float s = 0.f;
#pragma unroll
        for (int i = 0; i < 8; i++) s += red[i];
        g_cnt[lv][b] = s;
    }
}

// ---------------------------------------------------------------------------
// 2) prototype sums: one block per (channel, b, lv*2+half), __ldcs streaming
__global__ void k_proto(const float* __restrict__ s0, const float* __restrict__ s1,
                        const float* __restrict__ s2) {
    int ch = blockIdx.x, b = blockIdx.y, z = blockIdx.z, tid = threadIdx.x;
    int lv = z >> 1, half = z & 1;
    int hw = lv_hw(lv), h4 = hw >> 3;          // float4 elems per half
    const float* s = (lv == 0) ? s0 : (lv == 1 ? s1 : s2);
    const float4* row = (const float4*)(s + ((size_t)(b * D + ch)) * hw) + half * h4;
    const float4* m = (const float4*)(g_mask + lv_moff(lv) + b * hw) + half * h4;
    float sf = 0.f, sa = 0.f;
    for (int t = tid; t < h4; t += 128) {
        float4 x = __ldcs(row + t);
        float4 mm = m[t];
        sf += x.x * mm.x + x.y * mm.y + x.z * mm.z + x.w * mm.w;
        sa += x.x + x.y + x.z + x.w;
    }
    sf = warpSum(sf); sa = warpSum(sa);
    __shared__ float r1[4], r2[4];
    if ((tid & 31) == 0) { r1[tid >> 5] = sf; r2[tid >> 5] = sa; }
    __syncthreads();
    if (tid == 0) {
        g_sumfg[lv][half][b][ch]  = r1[0] + r1[1] + r1[2] + r1[3];
        g_sumall[lv][half][b][ch] = r2[0] + r2[1] + r2[2] + r2[3];
    }
}

// ---------------------------------------------------------------------------
// 3) prep: one WARP per (b,lv). 8 channels/thread, pure shfl reductions.
__global__ void k_prep(const float* __restrict__ r0, const float* __restrict__ r1,
                       const float* __restrict__ r2, float* __restrict__ out) {
    int b = blockIdx.x, lv = blockIdx.y, t = threadIdx.x;
    const float* R = (lv == 0) ? r0 : (lv == 1 ? r1 : r2);
    float cnt = g_cnt[lv][b];
    float hwf = (float)lv_hw(lv);

    float pf[8], pb[8], rn0[8], rn1[8], c0[8], c1[8], d0[8], d1[8];
    float nf = 0.f, nb = 0.f, nr0 = 0.f, nr1 = 0.f;
#pragma unroll
    for (int j = 0; j < 8; j++) {
        int c = t + 32 * j;
        float sfg = g_sumfg[lv][0][b][c] + g_sumfg[lv][1][b][c];
        float sal = g_sumall[lv][0][b][c] + g_sumall[lv][1][b][c];
        pf[j] = sfg / (cnt + 1e-6f);
        pb[j] = (sal - sfg) / (hwf - cnt + 1e-6f);
        nf += pf[j] * pf[j]; nb += pb[j] * pb[j];
        float v0 = R[c], v1 = R[D + c];
        rn0[j] = v0; rn1[j] = v1;
        nr0 += v0 * v0; nr1 += v1 * v1;
    }
    nf = warpSum(nf); nb = warpSum(nb); nr0 = warpSum(nr0); nr1 = warpSum(nr1);
    float sf_ = sqrtf(nf) + 1e-6f, sb_ = sqrtf(nb) + 1e-6f;
    float sr0 = sqrtf(nr0) + 1e-6f, sr1 = sqrtf(nr1) + 1e-6f;

    float m00 = 0.f, m01 = 0.f, m11 = 0.f;
#pragma unroll
    for (int j = 0; j < 8; j++) {
        c1[j] = pf[j] / sf_;
        c0[j] = pb[j] / sb_;
        rn0[j] = rn0[j] / sr0;
        rn1[j] = rn1[j] / sr1;
        m00 += c0[j] * c0[j]; m01 += c0[j] * c1[j]; m11 += c1[j] * c1[j];
    }
    m00 = warpSum(m00); m01 = warpSum(m01); m11 = warpSum(m11);
    float det = m00 * m11 - m01 * m01;
    float i00 = m11 / det, i01 = -m01 / det, i11 = m00 / det;

    float uf0 = 0.f, uf1 = 0.f, ub0 = 0.f, ub1 = 0.f;
#pragma unroll
    for (int j = 0; j < 8; j++) {
        int c = t + 32 * j;
        d0[j] = i00 * c0[j] + i01 * c1[j];
        d1[j] = i01 * c0[j] + i11 * c1[j];
        g_D[lv][b][0][c] = d0[j];
        g_D[lv][b][1][c] = d1[j];
        if (b == 0) { g_Rn[lv][0][c] = rn0[j]; g_Rn[lv][1][c] = rn1[j]; }
        uf0 += d0[j] * pf[j]; uf1 += d1[j] * pf[j];
        ub0 += d0[j] * pb[j]; ub1 += d1[j] * pb[j];
    }
    uf0 = warpSum(uf0); uf1 = warpSum(uf1);
    ub0 = warpSum(ub0); ub1 = warpSum(ub1);

    if (b == 0 && lv == 0) {
        float e00 = 0.f, e01 = 0.f, e11 = 0.f;
#pragma unroll
        for (int j = 0; j < 8; j++) {
            e00 += rn0[j] * rn0[j]; e01 += rn0[j] * rn1[j]; e11 += rn1[j] * rn1[j];
        }
        e00 = warpSum(e00); e01 = warpSum(e01); e11 = warpSum(e11);
        if (t == 0) { g_E[0] = e00; g_E[1] = e01; g_E[2] = e11; }
    }

#pragma unroll
    for (int j = 0; j < 8; j++) {
        int c = t + 32 * j;
        size_t rowbase = (size_t)(b * D + c) * NTOT;
        out[rowbase + POFF_FG + lv] = rn0[j] * uf0 + rn1[j] * uf1;
        out[rowbase + POFF_BG + lv] = rn0[j] * ub0 + rn1[j] * ub1;
    }
}

// ---------------------------------------------------------------------------
// 4a) Phase A: partial u over 32-channel chunk. 128-thread blocks for finer
//     wave balance: 11 slots per (b,which): lv0 8x128, lv1 2x128, lv2 1.
//     grid (11, NCHUNK, 16) = 1408 blocks. All loads __ldcs streaming.
__global__ void __launch_bounds__(128) k_rank2(
        const float* __restrict__ q0, const float* __restrict__ q1,
        const float* __restrict__ q2, const float* __restrict__ s0,
        const float* __restrict__ s1, const float* __restrict__ s2) {
    int z = blockIdx.z;
    int b = z >> 1, which = z & 1;
    int slot = blockIdx.x;                 // 0..10
    int lv, tile;
    if (slot < 8)       { lv = 0; tile = slot * 128; }
    else if (slot < 10) { lv = 1; tile = (slot - 8) * 128; }
    else                { lv = 2; tile = 0; }
    int hw = lv_hw(lv), hw4 = hw >> 2;
    int chunk = blockIdx.y, cbase = chunk * 32;
    int tid = threadIdx.x;

    __shared__ float sD0[32], sD1[32];
    if (tid < 32) {
        sD0[tid] = g_D[lv][b][0][cbase + tid];
        sD1[tid] = g_D[lv][b][1][cbase + tid];
    }
    __syncthreads();

    int p = tile + tid;
    if (p >= hw4) return;

    const float* f = (which == 0) ? (lv == 0 ? q0 : (lv == 1 ? q1 : q2))
                                  : (lv == 0 ? s0 : (lv == 1 ? s1 : s2));
    const float4* base = (const float4*)(f + (size_t)b * D * hw + (size_t)cbase * hw) + p;

    float u0x = 0.f, u0y = 0.f, u0z = 0.f, u0w = 0.f;
    float u1x = 0.f, u1y = 0.f, u1z = 0.f, u1w = 0.f;
#pragma unroll 16
    for (int i = 0; i < 32; i++) {
        float4 x = __ldcs(base + (size_t)i * hw4);
        float dd0 = sD0[i], dd1 = sD1[i];
        u0x += dd0 * x.x; u0y += dd0 * x.y; u0z += dd0 * x.z; u0w += dd0 * x.w;
        u1x += dd1 * x.x; u1y += dd1 * x.y; u1z += dd1 * x.z; u1w += dd1 * x.w;
    }

    int uoff = (which == 0) ? c_offQ[lv] : c_offS[lv];
    ((float4*)(g_upart[chunk][b][0] + uoff))[p] = make_float4(u0x, u0y, u0z, u0w);
    ((float4*)(g_upart[chunk][b][1] + uoff))[p] = make_float4(u1x, u1y, u1z, u1w);
}

// 4b) chunk fold: g_u = sum over 8 chunk partials, float2 granularity.
__global__ void k_usum() {
    int idx = blockIdx.x * 256 + threadIdx.x;          // float2 index
    const int P2 = UPLANE / 2;                          // 5376
    if (idx >= B * 2 * P2) return;
    int plane = idx / P2, i = idx % P2;
    int b = plane >> 1, comp = plane & 1;
    float2 a = make_float2(0.f, 0.f);
#pragma unroll
    for (int c = 0; c < NCHUNK; c++) {
        float2 v = ((const float2*)g_upart[c][b][comp])[i];
        a.x += v.x; a.y += v.y;
    }
    ((float2*)g_u[b][comp])[i] = a;
}

// 4c) Phase B: out[i,p] = R0[i]*u0[p] + R1[i]*u1[p]. Streaming stores.
//     Exact flattened grid: 11 active tiles per (b,which): lv0 8, lv1 2, lv2 1.
__global__ void k_expand(float* __restrict__ out) {
    int z = blockIdx.z;
    int b = z >> 1, which = z & 1;
    int tslot = blockIdx.x;                 // 0..10
    int lv, tile;
    if (tslot < 8)      { lv = 0; tile = tslot * 512; }
    else if (tslot < 10){ lv = 1; tile = (tslot - 8) * 512; }
    else                { lv = 2; tile = 0; }
    int hw = lv_hw(lv);
    int tid = threadIdx.x;
    int npix2 = min(512, hw - tile) >> 1;          // float2 slots (<=256)

    __shared__ float sR0[16], sR1[16];
    int ch0 = blockIdx.y * 16;
    if (tid < 16)          sR0[tid]      = g_Rn[lv][0][ch0 + tid];
    else if (tid < 32)     sR1[tid - 16] = g_Rn[lv][1][ch0 + tid - 16];
    __syncthreads();
    if (tid >= npix2) return;

    int uoff = (which == 0) ? c_offQ[lv] : c_offS[lv];
    float2 u0 = ((const float2*)(g_u[b][0] + uoff + tile))[tid];
    float2 u1 = ((const float2*)(g_u[b][1] + uoff + tile))[tid];

    size_t base = (size_t)(b * D + ch0) * NTOT + uoff + tile + 2 * tid;
#pragma unroll
    for (int i = 0; i < 16; i++) {
        float r0 = sR0[i], r1 = sR1[i];
        __stcs((float2*)(out + base + (size_t)i * NTOT),
               make_float2(r0 * u0.x + r1 * u1.x, r0 * u0.y + r1 * u1.y));
    }
}

// ---------------------------------------------------------------------------
// 5) top-32: register-resident u64 keys (sortable float bits | ~idx)
__global__ void k_topk(float* __restrict__ out) {
    int b = blockIdx.x, tid = threadIdx.x;
    int lane = tid & 31, wrp = tid >> 5;
    __shared__ unsigned long long swk[8];
    __shared__ unsigned long long s_best;
    __shared__ int s_idx[TOK_K];

    float cnt = g_cnt[0][b];
    float e00 = g_E[0], e01 = g_E[1], e11 = g_E[2];
    const float* m = g_mask + b * 4096;
    const int S0 = 5376;   // s lv0 offset in u plane

    unsigned long long key[16];
#pragma unroll
    for (int j = 0; j < 16; j++) {
        int t = tid + 256 * j;
        float u0 = g_u[b][0][S0 + t];
        float u1 = g_u[b][1][S0 + t];
        float s2 = e00 * u0 * u0 + 2.f * e01 * u0 * u1 + e11 * u1 * u1;
        bool valid = (cnt > 0.f) ? (m[t] >= 0.5f) : true;   // fallback_to_full
        unsigned int fb = __float_as_uint(s2);
        fb = (fb & 0x80000000u) ? ~fb : (fb | 0x80000000u); // sortable float bits
        unsigned int il = ~(unsigned int)t;                 // tie: lower idx wins
        key[j] = valid ? (((unsigned long long)fb << 32) | il)
                       : (unsigned long long)il;            // "-inf": high word 0
    }

    for (int sel = 0; sel < TOK_K; sel++) {
        unsigned long long mk = 0;
#pragma unroll
        for (int j = 0; j < 16; j++) mk = (key[j] > mk) ? key[j] : mk;
#pragma unroll
        for (int o = 16; o; o >>= 1) {
            unsigned long long other = __shfl_xor_sync(0xffffffffu, mk, o);
            if (other > mk) mk = other;
        }
        if (lane == 0) swk[wrp] = mk;
        __syncthreads();
        if (tid == 0) {
            unsigned long long best = swk[0];
#pragma unroll
            for (int w = 1; w < 8; w++) if (swk[w] > best) best = swk[w];
            s_best = best;
            s_idx[sel] = (int)(~(unsigned int)(best & 0xffffffffu));
        }
        __syncthreads();
        unsigned long long best = s_best;
#pragma unroll
        for (int j = 0; j < 16; j++) if (key[j] == best) key[j] = 0ull;
        __syncthreads();
    }

    // gather token columns: tid = channel
    float rn0 = g_Rn[0][0][tid], rn1 = g_Rn[0][1][tid];
    size_t rowbase = (size_t)(b * D + tid) * NTOT + TOK_OFF;
#pragma unroll
    for (int j = 0; j < TOK_K; j++) {
        int id = s_idx[j];
        out[rowbase + j] = rn0 * g_u[b][0][S0 + id] + rn1 * g_u[b][1][S0 + id];
    }
}

// ---------------------------------------------------------------------------
extern "C" void kernel_launch(void* const* d_in, const int* in_sizes, int n_in,
                              void* d_out, int out_size) {
    const float *q[3], *s[3], *r[3];
    if (in_sizes[1] == 8388608) {        // dict order q1,s1,r1,q2,s2,r2,q3,s3,r3
        q[0] = (const float*)d_in[0]; s[0] = (const float*)d_in[1]; r[0] = (const float*)d_in[2];
        q[1] = (const float*)d_in[3]; s[1] = (const float*)d_in[4]; r[1] = (const float*)d_in[5];
        q[2] = (const float*)d_in[6]; s[2] = (const float*)d_in[7]; r[2] = (const float*)d_in[8];
    } else {                             // signature order q1,q2,q3,s1,s2,s3,r1,r2,r3
        q[0] = (const float*)d_in[0]; q[1] = (const float*)d_in[1]; q[2] = (const float*)d_in[2];
        s[0] = (const float*)d_in[3]; s[1] = (const float*)d_in[4]; s[2] = (const float*)d_in[5];
        r[0] = (const float*)d_in[6]; r[1] = (const float*)d_in[7]; r[2] = (const float*)d_in[8];
    }
    const int* sm = (const int*)d_in[9];
    float* out = (float*)d_out;

    // Side stream + events for topk || expand overlap (created once, on the
    // uncaptured correctness call; reused inside graph capture thereafter).
    static cudaStream_t s2 = nullptr;
    static cudaEvent_t evFork = nullptr, evJoin = nullptr;
    if (s2 == nullptr) {
        cudaStreamCreateWithFlags(&s2, cudaStreamNonBlocking);
        cudaEventCreateWithFlags(&evFork, cudaEventDisableTiming);
        cudaEventCreateWithFlags(&evJoin, cudaEventDisableTiming);
    }

    k_mask<<<dim3(B, 3), 256>>>(sm);
    k_proto<<<dim3(D, B, 6), 128>>>(s[0], s[1], s[2]);
    k_prep<<<dim3(B, 3), 32>>>(r[0], r[1], r[2], out);
    k_rank2<<<dim3(11, NCHUNK, 16), 128>>>(q[0], q[1], q[2], s[0], s[1], s[2]);
    k_usum<<<336, 256>>>();

    // fork: topk on side stream, concurrent with expand on main stream
    cudaEventRecord(evFork, 0);
    cudaStreamWaitEvent(s2, evFork, 0);
    k_topk<<<B, 256, 0, s2>>>(out);
    k_expand<<<dim3(11, 16, 16), 256>>>(out);
    cudaEventRecord(evJoin, s2);
    cudaStreamWaitEvent(0, evJoin, 0);
}